// round 6
// baseline (speedup 1.0000x reference)
#include <cuda_runtime.h>
#include <cstdint>

#define N_NODES 50000
#define N_EDGES 800000
#define D 128
#define NUM_GRAPHS 128
#define N_LAYERS 4
#define BN_EPS 1e-5f

#define MT 128
#define GEMM_GRID ((N_NODES + MT - 1) / MT)

#define SCAN_BLK 1024
#define SCAN_NBLK ((N_NODES + SCAN_BLK - 1) / SCAN_BLK)

// ---- smem float-index map for gemm_mma ----
#define SB1   0
#define SB2   128
#define SSUM  256
#define SSQ   384
#define SAH   512                  // 128 x 132 (A hi / Z staging fp32)
#define SAL   (SAH + 128 * 132)    // 128 x 132 (A lo)
#define SWH   (SAL + 128 * 132)    // 64 x 132 (W hi, K-half)
#define SWL   (SWH + 64 * 132)     // 64 x 132 (W lo, K-half)
#define SM_FLOATS (SWL + 64 * 132)
#define SM_BYTES (SM_FLOATS * 4)   // 204800

// ---------------- device scratch ----------------
__device__ float g_a[(size_t)N_NODES * D];
__device__ float g_z[(size_t)N_NODES * D];
__device__ int   g_deg[N_NODES];
__device__ int   g_ptr[N_NODES + 1];
__device__ int   g_cursor[N_NODES];
__device__ int   g_csr[N_EDGES];
__device__ int   g_bsum[SCAN_NBLK];
__device__ float g_stats[(N_LAYERS - 1) * 2 * D];
__device__ int   g_idx64;

__device__ __forceinline__ int load_idx(const void* p, int i) {
    if (g_idx64) return (int)((const long long*)p)[i];
    return ((const int*)p)[i];
}

__device__ __forceinline__ void cvt_hilo(float v, uint32_t& hi, uint32_t& lo) {
    asm("cvt.rna.tf32.f32 %0, %1;" : "=r"(hi) : "f"(v));
    float l = v - __uint_as_float(hi);
    asm("cvt.rna.tf32.f32 %0, %1;" : "=r"(lo) : "f"(l));
}

__device__ __forceinline__ void mma8(float* c, uint32_t a0, uint32_t a1,
                                     uint32_t a2, uint32_t a3,
                                     uint32_t b0, uint32_t b1) {
    asm volatile(
        "mma.sync.aligned.m16n8k8.row.col.f32.tf32.tf32.f32 "
        "{%0,%1,%2,%3}, {%4,%5,%6,%7}, {%8,%9}, {%0,%1,%2,%3};"
        : "+f"(c[0]), "+f"(c[1]), "+f"(c[2]), "+f"(c[3])
        : "r"(a0), "r"(a1), "r"(a2), "r"(a3), "r"(b0), "r"(b1));
}

// ---------------- detect dtype + zero scratch (launch 0) ----------------
__global__ void detect_zero_kernel(const void* ei, float* __restrict__ out) {
    int i = blockIdx.x * blockDim.x + threadIdx.x;
    int stride = gridDim.x * blockDim.x;
    for (int t = i; t < N_NODES; t += stride) g_deg[t] = 0;
    for (int t = i; t < (N_LAYERS - 1) * 2 * D; t += stride) g_stats[t] = 0.0f;
    for (int t = i; t < NUM_GRAPHS * D; t += stride) out[t] = 0.0f;

    if (blockIdx.x == 0) {
        __shared__ int any_nonzero;
        const int* a = (const int*)ei;
        if (threadIdx.x == 0) any_nonzero = 0;
        __syncthreads();
        int step = (2 * N_EDGES) / 256;
        int pos = (threadIdx.x * step) | 1;
        if (threadIdx.x < 256 && a[pos] != 0) any_nonzero = 1;
        __syncthreads();
        if (threadIdx.x == 0) g_idx64 = any_nonzero ? 0 : 1;
    }
}

// ---------------- CSR build ----------------
__global__ void hist_kernel(const void* __restrict__ ei) {
    int e = blockIdx.x * blockDim.x + threadIdx.x;
    if (e < N_EDGES) {
        int dst = load_idx(ei, N_EDGES + e);
        if (dst >= 0 && dst < N_NODES) atomicAdd(&g_deg[dst], 1);
    }
}

__global__ void scan_part_kernel() {
    __shared__ int wsum[32];
    const int tid = threadIdx.x;
    const int lane = tid & 31, wid = tid >> 5;
    int idx = blockIdx.x * SCAN_BLK + tid;
    int v = (idx < N_NODES) ? g_deg[idx] : 0;
    int s = v;
    #pragma unroll
    for (int off = 1; off < 32; off <<= 1) {
        int t = __shfl_up_sync(0xffffffffu, s, off);
        if (lane >= off) s += t;
    }
    if (lane == 31) wsum[wid] = s;
    __syncthreads();
    if (wid == 0) {
        int ws = wsum[lane];
        #pragma unroll
        for (int off = 1; off < 32; off <<= 1) {
            int t = __shfl_up_sync(0xffffffffu, ws, off);
            if (lane >= off) ws += t;
        }
        wsum[lane] = ws;
    }
    __syncthreads();
    int incl = s + ((wid > 0) ? wsum[wid - 1] : 0);
    if (idx < N_NODES) g_ptr[idx + 1] = incl;
    if (tid == SCAN_BLK - 1) g_bsum[blockIdx.x] = incl;
}

// each block computes its own carry from the (<=49) block sums, adds, fills cursor
__global__ void scan_topadd_kernel() {
    __shared__ int carry_s;
    const int tid = threadIdx.x;
    if (tid == 0) {
        int run = 0;
        for (int b = 0; b < (int)blockIdx.x; b++) run += g_bsum[b];
        carry_s = run;
    }
    __syncthreads();
    int idx = blockIdx.x * SCAN_BLK + tid;
    if (idx < N_NODES) {
        int p = g_ptr[idx + 1] + carry_s;
        g_ptr[idx + 1] = p;
        g_cursor[idx + 1] = p;
    }
    if (idx == 0) { g_ptr[0] = 0; g_cursor[0] = 0; }
}

__global__ void fill_kernel(const void* __restrict__ ei) {
    int e = blockIdx.x * blockDim.x + threadIdx.x;
    if (e >= N_EDGES) return;
    int src = load_idx(ei, e);
    int dst = load_idx(ei, N_EDGES + e);
    if (dst < 0 || dst >= N_NODES || src < 0 || src >= N_NODES) return;
    int p = atomicAdd(&g_cursor[dst], 1);
    if (p >= 0 && p < N_EDGES) g_csr[p] = src;
}

// ---------------- gather with fused BN+ReLU of previous layer (launch 5) ----------------
__global__ void __launch_bounds__(256) gather_kernel(
    const float* __restrict__ x, const float* __restrict__ eps_arr,
    const float* __restrict__ gamma, const float* __restrict__ beta,
    int layer)
{
    __shared__ float ssc[D], ssh[D];
    const int tid = threadIdx.x;
    const int apply_bn = (layer > 0);
    if (apply_bn && tid < D) {
        const float* stats = &g_stats[(layer - 1) * 2 * D];
        const float invN = 1.0f / (float)N_NODES;
        float mu = stats[tid] * invN;
        float var = stats[D + tid] * invN - mu * mu;
        float sc = rsqrtf(var + BN_EPS) * gamma[tid];
        ssc[tid] = sc;
        ssh[tid] = beta[tid] - mu * sc;
    }
    __syncthreads();

    const int lane = tid & 31, wid = tid >> 5;
    const int r = blockIdx.x * 8 + wid;
    if (r >= N_NODES) return;

    float4 sc4 = make_float4(1.f, 1.f, 1.f, 1.f);
    float4 sh4 = make_float4(0.f, 0.f, 0.f, 0.f);
    if (apply_bn) {
        sc4 = *(const float4*)&ssc[lane * 4];
        sh4 = *(const float4*)&ssh[lane * 4];
    }
    const float ep = 1.0f + eps_arr[layer];
    const float4* __restrict__ h4 = apply_bn ? (const float4*)g_z : (const float4*)x;

    float4 v = h4[r * 32 + lane];
    float4 acc;
    if (apply_bn) {
        acc.x = ep * fmaxf(v.x * sc4.x + sh4.x, 0.0f);
        acc.y = ep * fmaxf(v.y * sc4.y + sh4.y, 0.0f);
        acc.z = ep * fmaxf(v.z * sc4.z + sh4.z, 0.0f);
        acc.w = ep * fmaxf(v.w * sc4.w + sh4.w, 0.0f);
    } else {
        acc.x = ep * v.x; acc.y = ep * v.y; acc.z = ep * v.z; acc.w = ep * v.w;
    }

    int e = g_ptr[r], end = g_ptr[r + 1];
    while (e < end) {
        int n = end - e;
        int sidx[8];
        #pragma unroll
        for (int t = 0; t < 8; t++) sidx[t] = (t < n) ? g_csr[e + t] : -1;
        #pragma unroll
        for (int t = 0; t < 8; t++) {
            if (sidx[t] >= 0) {
                float4 u = h4[sidx[t] * 32 + lane];
                if (apply_bn) {
                    acc.x += fmaxf(u.x * sc4.x + sh4.x, 0.0f);
                    acc.y += fmaxf(u.y * sc4.y + sh4.y, 0.0f);
                    acc.z += fmaxf(u.z * sc4.z + sh4.z, 0.0f);
                    acc.w += fmaxf(u.w * sc4.w + sh4.w, 0.0f);
                } else {
                    acc.x += u.x; acc.y += u.y; acc.z += u.z; acc.w += u.w;
                }
            }
        }
        e += 8;
    }
    ((float4*)g_a)[r * 32 + lane] = acc;
}

// ---------------- one 128x128x64 half-K GEMM pass (3xTF32) ----------------
__device__ __forceinline__ void gemm_half(
    const float* __restrict__ smf, float (&acc)[4][4][4],
    int wr, int wc, int g, int t, int h)
{
    const uint32_t* __restrict__ ah = (const uint32_t*)smf + SAH;
    const uint32_t* __restrict__ al = (const uint32_t*)smf + SAL;
    const uint32_t* __restrict__ wh = (const uint32_t*)smf + SWH;
    const uint32_t* __restrict__ wl = (const uint32_t*)smf + SWL;
    #pragma unroll 1
    for (int ks = 0; ks < 8; ks++) {
        const int ka = h * 64 + ks * 8 + t;   // A column
        const int kw = ks * 8 + t;            // W row (within half)
        uint32_t ahi[4][4], alo[4][4];
        #pragma unroll
        for (int i = 0; i < 4; i++) {
            int rb = (wr + i * 16 + g) * 132 + ka;
            ahi[i][0] = ah[rb];
            ahi[i][1] = ah[rb + 8 * 132];
            ahi[i][2] = ah[rb + 4];
            ahi[i][3] = ah[rb + 8 * 132 + 4];
            alo[i][0] = al[rb];
            alo[i][1] = al[rb + 8 * 132];
            alo[i][2] = al[rb + 4];
            alo[i][3] = al[rb + 8 * 132 + 4];
        }
        #pragma unroll
        for (int j = 0; j < 4; j++) {
            int nb = kw * 132 + wc + j * 8 + g;
            uint32_t bh0 = wh[nb], bh1 = wh[nb + 4 * 132];
            uint32_t bl0 = wl[nb], bl1 = wl[nb + 4 * 132];
            #pragma unroll
            for (int i = 0; i < 4; i++) {
                mma8(acc[i][j], ahi[i][0], ahi[i][1], ahi[i][2], ahi[i][3], bh0, bh1);
                mma8(acc[i][j], ahi[i][0], ahi[i][1], ahi[i][2], ahi[i][3], bl0, bl1);
                mma8(acc[i][j], alo[i][0], alo[i][1], alo[i][2], alo[i][3], bh0, bh1);
            }
        }
    }
}

// load one K-half (64 rows) of W, split hi/lo. Wg[(h*64+kk)*128 + n] -> [kk*132+n]
__device__ __forceinline__ void load_w_half(
    float* smf, const float* __restrict__ Wg, int h, int tid)
{
    uint32_t* wh = (uint32_t*)smf + SWH;
    uint32_t* wl = (uint32_t*)smf + SWL;
    const float* src = Wg + (size_t)h * 64 * 128;
    #pragma unroll
    for (int it = 0; it < 32; it++) {
        int idx = tid + it * 256;        // 8192 elems
        int kk = idx >> 7, n = idx & 127;
        uint32_t hi, lo;
        cvt_hilo(src[idx], hi, lo);
        wh[kk * 132 + n] = hi;
        wl[kk * 132 + n] = lo;
    }
}

// ---------------- GEMM kernel: Z = relu(A@W1+b1)@W2 + b2 + epilogue ----------------
__global__ void __launch_bounds__(256, 1) gemm_mma(
    const float* __restrict__ W1, const float* __restrict__ b1,
    const float* __restrict__ W2, const float* __restrict__ b2,
    int layer, float* __restrict__ out, const void* __restrict__ batch, int last)
{
    extern __shared__ float smf[];
    uint32_t* sah = (uint32_t*)smf + SAH;
    uint32_t* sal = (uint32_t*)smf + SAL;
    const int tid = threadIdx.x;
    const int wid = tid >> 5, lane = tid & 31;
    const int g = lane >> 2, t = lane & 3;
    const int wr = (wid >> 2) * 64;
    const int wc = (wid & 3) * 32;
    const int r0 = blockIdx.x * MT;

    if (tid < 128) {
        smf[SB1 + tid] = b1[tid];
        smf[SB2 + tid] = b2[tid];
        smf[SSUM + tid] = 0.0f;
        smf[SSQ + tid] = 0.0f;
    }

    // fill A tile split hi/lo (column-contiguous: conflict-free stores, coalesced loads)
    #pragma unroll
    for (int it = 0; it < 64; it++) {
        int idx = tid + it * 256;       // 16384 elems
        int m = idx >> 7, c = idx & 127;
        float v = 0.0f;
        if (r0 + m < N_NODES) v = g_a[(size_t)(r0 + m) * D + c];
        uint32_t hi, lo;
        cvt_hilo(v, hi, lo);
        sah[m * 132 + c] = hi;
        sal[m * 132 + c] = lo;
    }

    float acc[4][4][4];
    #pragma unroll
    for (int i = 0; i < 4; i++)
        #pragma unroll
        for (int j = 0; j < 4; j++)
            #pragma unroll
            for (int c = 0; c < 4; c++) acc[i][j][c] = 0.0f;

    // ---- GEMM1 over two K-halves ----
    #pragma unroll 1
    for (int h = 0; h < 2; h++) {
        load_w_half(smf, W1, h, tid);
        __syncthreads();
        gemm_half(smf, acc, wr, wc, g, t, h);
        __syncthreads();
    }

    // T = relu(acc + b1) -> split hi/lo back into sA
    #pragma unroll
    for (int i = 0; i < 4; i++) {
        #pragma unroll
        for (int j = 0; j < 4; j++) {
            int c0 = wc + j * 8 + 2 * t;
            int rA = wr + i * 16 + g;
            float bb0 = smf[SB1 + c0], bb1 = smf[SB1 + c0 + 1];
            float v00 = fmaxf(acc[i][j][0] + bb0, 0.0f);
            float v01 = fmaxf(acc[i][j][1] + bb1, 0.0f);
            float v10 = fmaxf(acc[i][j][2] + bb0, 0.0f);
            float v11 = fmaxf(acc[i][j][3] + bb1, 0.0f);
            uint32_t hi, lo;
            cvt_hilo(v00, hi, lo); sah[rA * 132 + c0] = hi;       sal[rA * 132 + c0] = lo;
            cvt_hilo(v01, hi, lo); sah[rA * 132 + c0 + 1] = hi;   sal[rA * 132 + c0 + 1] = lo;
            cvt_hilo(v10, hi, lo); sah[(rA + 8) * 132 + c0] = hi; sal[(rA + 8) * 132 + c0] = lo;
            cvt_hilo(v11, hi, lo); sah[(rA + 8) * 132 + c0 + 1] = hi; sal[(rA + 8) * 132 + c0 + 1] = lo;
            acc[i][j][0] = 0.0f; acc[i][j][1] = 0.0f;
            acc[i][j][2] = 0.0f; acc[i][j][3] = 0.0f;
        }
    }
    __syncthreads();

    // ---- GEMM2 over two K-halves ----
    #pragma unroll 1
    for (int h = 0; h < 2; h++) {
        load_w_half(smf, W2, h, tid);
        __syncthreads();
        gemm_half(smf, acc, wr, wc, g, t, h);
        __syncthreads();
    }

    // stage z = acc + b2 into SAH region as fp32
    #pragma unroll
    for (int i = 0; i < 4; i++) {
        #pragma unroll
        for (int j = 0; j < 4; j++) {
            int c0 = wc + j * 8 + 2 * t;
            int rA = wr + i * 16 + g;
            float bb0 = smf[SB2 + c0], bb1 = smf[SB2 + c0 + 1];
            float2 u0 = make_float2(acc[i][j][0] + bb0, acc[i][j][1] + bb1);
            float2 u1 = make_float2(acc[i][j][2] + bb0, acc[i][j][3] + bb1);
            *(float2*)&smf[SAH + rA * 132 + c0] = u0;
            *(float2*)&smf[SAH + (rA + 8) * 132 + c0] = u1;
        }
    }
    __syncthreads();

    const int col4 = tid & 31;
    if (!last) {
        float s[4] = {0, 0, 0, 0}, q[4] = {0, 0, 0, 0};
        #pragma unroll
        for (int it = 0; it < 16; it++) {
            int row = (tid >> 5) + it * 8;
            int r = r0 + row;
            if (r < N_NODES) {
                float4 z4 = *(const float4*)&smf[SAH + row * 132 + col4 * 4];
                *(float4*)&g_z[(size_t)r * D + col4 * 4] = z4;
                s[0] += z4.x; q[0] += z4.x * z4.x;
                s[1] += z4.y; q[1] += z4.y * z4.y;
                s[2] += z4.z; q[2] += z4.z * z4.z;
                s[3] += z4.w; q[3] += z4.w * z4.w;
            }
        }
        #pragma unroll
        for (int j = 0; j < 4; j++) {
            atomicAdd(&smf[SSUM + col4 * 4 + j], s[j]);
            atomicAdd(&smf[SSQ + col4 * 4 + j], q[j]);
        }
        __syncthreads();
        if (tid < 128) {
            atomicAdd(&g_stats[layer * 2 * D + tid], smf[SSUM + tid]);
            atomicAdd(&g_stats[layer * 2 * D + D + tid], smf[SSQ + tid]);
        }
    } else {
        int gcur = -1;
        float a0 = 0, a1 = 0, a2 = 0, a3 = 0;
        #pragma unroll 1
        for (int it = 0; it < 16; it++) {
            int row = (tid >> 5) + it * 8;
            int r = r0 + row;
            if (r < N_NODES) {
                float4 z4 = *(const float4*)&smf[SAH + row * 132 + col4 * 4];
                int gg = load_idx(batch, r);
                if (gg == gcur) {
                    a0 += z4.x; a1 += z4.y; a2 += z4.z; a3 += z4.w;
                } else {
                    if (gcur >= 0 && gcur < NUM_GRAPHS) {
                        atomicAdd(&out[gcur * D + col4 * 4 + 0], a0);
                        atomicAdd(&out[gcur * D + col4 * 4 + 1], a1);
                        atomicAdd(&out[gcur * D + col4 * 4 + 2], a2);
                        atomicAdd(&out[gcur * D + col4 * 4 + 3], a3);
                    }
                    gcur = gg; a0 = z4.x; a1 = z4.y; a2 = z4.z; a3 = z4.w;
                }
            }
        }
        if (gcur >= 0 && gcur < NUM_GRAPHS) {
            atomicAdd(&out[gcur * D + col4 * 4 + 0], a0);
            atomicAdd(&out[gcur * D + col4 * 4 + 1], a1);
            atomicAdd(&out[gcur * D + col4 * 4 + 2], a2);
            atomicAdd(&out[gcur * D + col4 * 4 + 3], a3);
        }
    }
}

// ---------------- launch ----------------
extern "C" void kernel_launch(void* const* d_in, const int* in_sizes, int n_in,
                              void* d_out, int out_size) {
    const float* x     = (const float*)d_in[0];
    const void*  ei    = d_in[1];
    const void*  batch = d_in[2];
    const float* W1    = (const float*)d_in[3];
    const float* b1    = (const float*)d_in[4];
    const float* W2    = (const float*)d_in[5];
    const float* b2    = (const float*)d_in[6];
    const float* eps   = (const float*)d_in[7];
    const float* gamma = (const float*)d_in[8];
    const float* beta  = (const float*)d_in[9];
    float* out = (float*)d_out;

    cudaFuncSetAttribute(gemm_mma, cudaFuncAttributeMaxDynamicSharedMemorySize,
                         SM_BYTES);

    detect_zero_kernel<<<64, 256>>>(ei, out);              // 0
    hist_kernel<<<(N_EDGES + 255) / 256, 256>>>(ei);       // 1
    scan_part_kernel<<<SCAN_NBLK, SCAN_BLK>>>();           // 2
    scan_topadd_kernel<<<SCAN_NBLK, SCAN_BLK>>>();         // 3
    fill_kernel<<<(N_EDGES + 255) / 256, 256>>>(ei);       // 4

    for (int i = 0; i < N_LAYERS; i++) {
        gather_kernel<<<(N_NODES + 7) / 8, 256>>>(          // 5 on first iter
            x, eps, gamma + (i > 0 ? (i - 1) * D : 0),
            beta + (i > 0 ? (i - 1) * D : 0), i);
        gemm_mma<<<GEMM_GRID, 256, SM_BYTES>>>(
            W1 + i * D * D, b1 + i * D, W2 + i * D * D, b2 + i * D,
            i, out, batch, (i == N_LAYERS - 1) ? 1 : 0);
    }
}

// round 7
// speedup vs baseline: 1.0251x; 1.0251x over previous
#include <cuda_runtime.h>
#include <cstdint>

#define N_NODES 50000
#define N_EDGES 800000
#define D 128
#define NUM_GRAPHS 128
#define N_LAYERS 4
#define BN_EPS 1e-5f

#define MT 128
#define GEMM_GRID ((N_NODES + MT - 1) / MT)

#define SCAN_BLK 1024
#define SCAN_NBLK ((N_NODES + SCAN_BLK - 1) / SCAN_BLK)

// ---- smem float-index map for gemm_mma (103424 bytes -> 2 CTAs/SM) ----
#define SB1   0
#define SB2   128
#define SSUM  256
#define SSQ   384
#define SA    512                  // 128 x 132 fp32 (A tile / T tile / Z staging)
#define SWH   (SA + 128 * 132)     // 32 x 132 u32 (W hi, K-quarter)
#define SWL   (SWH + 32 * 132)     // 32 x 132 u32 (W lo, K-quarter)
#define SM_FLOATS (SWL + 32 * 132)
#define SM_BYTES (SM_FLOATS * 4)   // 103424

// ---------------- device scratch ----------------
__device__ float g_a[(size_t)N_NODES * D];
__device__ float g_z[(size_t)N_NODES * D];
__device__ int   g_deg[N_NODES];
__device__ int   g_ptr[N_NODES + 1];
__device__ int   g_cursor[N_NODES];
__device__ int   g_csr[N_EDGES];
__device__ int   g_bsum[SCAN_NBLK];
__device__ float g_stats[(N_LAYERS - 1) * 2 * D];
__device__ int   g_idx64;

__device__ __forceinline__ int load_idx(const void* p, int i) {
    if (g_idx64) return (int)((const long long*)p)[i];
    return ((const int*)p)[i];
}

__device__ __forceinline__ void cvt_hilo(float v, uint32_t& hi, uint32_t& lo) {
    asm("cvt.rna.tf32.f32 %0, %1;" : "=r"(hi) : "f"(v));
    float l = v - __uint_as_float(hi);
    asm("cvt.rna.tf32.f32 %0, %1;" : "=r"(lo) : "f"(l));
}

__device__ __forceinline__ void mma8(float* c, uint32_t a0, uint32_t a1,
                                     uint32_t a2, uint32_t a3,
                                     uint32_t b0, uint32_t b1) {
    asm volatile(
        "mma.sync.aligned.m16n8k8.row.col.f32.tf32.tf32.f32 "
        "{%0,%1,%2,%3}, {%4,%5,%6,%7}, {%8,%9}, {%0,%1,%2,%3};"
        : "+f"(c[0]), "+f"(c[1]), "+f"(c[2]), "+f"(c[3])
        : "r"(a0), "r"(a1), "r"(a2), "r"(a3), "r"(b0), "r"(b1));
}

// ---------------- detect dtype + zero scratch (launch 0) ----------------
__global__ void detect_zero_kernel(const void* ei, float* __restrict__ out) {
    int i = blockIdx.x * blockDim.x + threadIdx.x;
    int stride = gridDim.x * blockDim.x;
    for (int t = i; t < N_NODES; t += stride) g_deg[t] = 0;
    for (int t = i; t < (N_LAYERS - 1) * 2 * D; t += stride) g_stats[t] = 0.0f;
    for (int t = i; t < NUM_GRAPHS * D; t += stride) out[t] = 0.0f;

    if (blockIdx.x == 0) {
        __shared__ int any_nonzero;
        const int* a = (const int*)ei;
        if (threadIdx.x == 0) any_nonzero = 0;
        __syncthreads();
        int step = (2 * N_EDGES) / 256;
        int pos = (threadIdx.x * step) | 1;
        if (a[pos] != 0) any_nonzero = 1;
        __syncthreads();
        if (threadIdx.x == 0) g_idx64 = any_nonzero ? 0 : 1;
    }
}

// ---------------- CSR build ----------------
__global__ void hist_kernel(const void* __restrict__ ei) {
    int e = blockIdx.x * blockDim.x + threadIdx.x;
    if (e < N_EDGES) {
        int dst = load_idx(ei, N_EDGES + e);
        if (dst >= 0 && dst < N_NODES) atomicAdd(&g_deg[dst], 1);
    }
}

__global__ void scan_part_kernel() {
    __shared__ int wsum[32];
    const int tid = threadIdx.x;
    const int lane = tid & 31, wid = tid >> 5;
    int idx = blockIdx.x * SCAN_BLK + tid;
    int v = (idx < N_NODES) ? g_deg[idx] : 0;
    int s = v;
    #pragma unroll
    for (int off = 1; off < 32; off <<= 1) {
        int t = __shfl_up_sync(0xffffffffu, s, off);
        if (lane >= off) s += t;
    }
    if (lane == 31) wsum[wid] = s;
    __syncthreads();
    if (wid == 0) {
        int ws = wsum[lane];
        #pragma unroll
        for (int off = 1; off < 32; off <<= 1) {
            int t = __shfl_up_sync(0xffffffffu, ws, off);
            if (lane >= off) ws += t;
        }
        wsum[lane] = ws;
    }
    __syncthreads();
    int incl = s + ((wid > 0) ? wsum[wid - 1] : 0);
    if (idx < N_NODES) g_ptr[idx + 1] = incl;
    if (tid == SCAN_BLK - 1) g_bsum[blockIdx.x] = incl;
}

__global__ void scan_topadd_kernel() {
    __shared__ int carry_s;
    const int tid = threadIdx.x;
    if (tid == 0) {
        int run = 0;
        for (int b = 0; b < (int)blockIdx.x; b++) run += g_bsum[b];
        carry_s = run;
    }
    __syncthreads();
    int idx = blockIdx.x * SCAN_BLK + tid;
    if (idx < N_NODES) {
        int p = g_ptr[idx + 1] + carry_s;
        g_ptr[idx + 1] = p;
        g_cursor[idx + 1] = p;
    }
    if (idx == 0) { g_ptr[0] = 0; g_cursor[0] = 0; }
}

__global__ void fill_kernel(const void* __restrict__ ei) {
    int e = blockIdx.x * blockDim.x + threadIdx.x;
    if (e >= N_EDGES) return;
    int src = load_idx(ei, e);
    int dst = load_idx(ei, N_EDGES + e);
    if (dst < 0 || dst >= N_NODES || src < 0 || src >= N_NODES) return;
    int p = atomicAdd(&g_cursor[dst], 1);
    if (p >= 0 && p < N_EDGES) g_csr[p] = src;
}

// ---------------- gather with fused BN+ReLU of previous layer ----------------
__global__ void __launch_bounds__(256) gather_kernel(
    const float* __restrict__ x, const float* __restrict__ eps_arr,
    const float* __restrict__ gamma, const float* __restrict__ beta,
    int layer)
{
    __shared__ float ssc[D], ssh[D];
    const int tid = threadIdx.x;
    const int apply_bn = (layer > 0);
    if (apply_bn && tid < D) {
        const float* stats = &g_stats[(layer - 1) * 2 * D];
        const float invN = 1.0f / (float)N_NODES;
        float mu = stats[tid] * invN;
        float var = stats[D + tid] * invN - mu * mu;
        float sc = rsqrtf(var + BN_EPS) * gamma[tid];
        ssc[tid] = sc;
        ssh[tid] = beta[tid] - mu * sc;
    }
    __syncthreads();

    const int lane = tid & 31, wid = tid >> 5;
    const int r = blockIdx.x * 8 + wid;
    if (r >= N_NODES) return;

    float4 sc4 = make_float4(1.f, 1.f, 1.f, 1.f);
    float4 sh4 = make_float4(0.f, 0.f, 0.f, 0.f);
    if (apply_bn) {
        sc4 = *(const float4*)&ssc[lane * 4];
        sh4 = *(const float4*)&ssh[lane * 4];
    }
    const float ep = 1.0f + eps_arr[layer];
    const float4* __restrict__ h4 = apply_bn ? (const float4*)g_z : (const float4*)x;

    float4 v = h4[r * 32 + lane];
    float4 acc;
    if (apply_bn) {
        acc.x = ep * fmaxf(v.x * sc4.x + sh4.x, 0.0f);
        acc.y = ep * fmaxf(v.y * sc4.y + sh4.y, 0.0f);
        acc.z = ep * fmaxf(v.z * sc4.z + sh4.z, 0.0f);
        acc.w = ep * fmaxf(v.w * sc4.w + sh4.w, 0.0f);
    } else {
        acc.x = ep * v.x; acc.y = ep * v.y; acc.z = ep * v.z; acc.w = ep * v.w;
    }

    const int e0 = g_ptr[r], end = g_ptr[r + 1];
    for (int base = e0; base < end; base += 32) {
        const int cnt = min(end - base, 32);
        int myidx = (lane < cnt) ? g_csr[base + lane] : 0;
        int t0 = 0;
        for (; t0 + 8 <= cnt; t0 += 8) {
            int ss[8];
            #pragma unroll
            for (int t = 0; t < 8; t++) ss[t] = __shfl_sync(0xffffffffu, myidx, t0 + t);
            float4 u[8];
            #pragma unroll
            for (int t = 0; t < 8; t++) u[t] = h4[(size_t)ss[t] * 32 + lane];
            #pragma unroll
            for (int t = 0; t < 8; t++) {
                if (apply_bn) {
                    acc.x += fmaxf(u[t].x * sc4.x + sh4.x, 0.0f);
                    acc.y += fmaxf(u[t].y * sc4.y + sh4.y, 0.0f);
                    acc.z += fmaxf(u[t].z * sc4.z + sh4.z, 0.0f);
                    acc.w += fmaxf(u[t].w * sc4.w + sh4.w, 0.0f);
                } else {
                    acc.x += u[t].x; acc.y += u[t].y;
                    acc.z += u[t].z; acc.w += u[t].w;
                }
            }
        }
        for (; t0 < cnt; t0++) {
            int s = __shfl_sync(0xffffffffu, myidx, t0);
            float4 u = h4[(size_t)s * 32 + lane];
            if (apply_bn) {
                acc.x += fmaxf(u.x * sc4.x + sh4.x, 0.0f);
                acc.y += fmaxf(u.y * sc4.y + sh4.y, 0.0f);
                acc.z += fmaxf(u.z * sc4.z + sh4.z, 0.0f);
                acc.w += fmaxf(u.w * sc4.w + sh4.w, 0.0f);
            } else {
                acc.x += u.x; acc.y += u.y; acc.z += u.z; acc.w += u.w;
            }
        }
    }
    ((float4*)g_a)[r * 32 + lane] = acc;
}

// ---------------- one 128x128x32 quarter-K GEMM pass (3xTF32) ----------------
// A fp32 in smem (cvt in-register); W hi/lo tf32 in smem.
__device__ __forceinline__ void gemm_quarter(
    const float* __restrict__ smf, float (&acc)[4][4][4],
    int wr, int wc, int g, int t, int h)
{
    const uint32_t* __restrict__ wh = (const uint32_t*)smf + SWH;
    const uint32_t* __restrict__ wl = (const uint32_t*)smf + SWL;
    #pragma unroll 1
    for (int ks = 0; ks < 4; ks++) {
        const int ka = h * 32 + ks * 8 + t;   // A column
        const int kw = ks * 8 + t;            // W row within quarter
        uint32_t ahi[4][4], alo[4][4];
        #pragma unroll
        for (int i = 0; i < 4; i++) {
            int rb = SA + (wr + i * 16 + g) * 132 + ka;
            float v0 = smf[rb];
            float v1 = smf[rb + 8 * 132];
            float v2 = smf[rb + 4];
            float v3 = smf[rb + 8 * 132 + 4];
            cvt_hilo(v0, ahi[i][0], alo[i][0]);
            cvt_hilo(v1, ahi[i][1], alo[i][1]);
            cvt_hilo(v2, ahi[i][2], alo[i][2]);
            cvt_hilo(v3, ahi[i][3], alo[i][3]);
        }
        #pragma unroll
        for (int j = 0; j < 4; j++) {
            int nb = kw * 132 + wc + j * 8 + g;
            uint32_t bh0 = wh[nb], bh1 = wh[nb + 4 * 132];
            uint32_t bl0 = wl[nb], bl1 = wl[nb + 4 * 132];
            #pragma unroll
            for (int i = 0; i < 4; i++) {
                mma8(acc[i][j], ahi[i][0], ahi[i][1], ahi[i][2], ahi[i][3], bh0, bh1);
                mma8(acc[i][j], ahi[i][0], ahi[i][1], ahi[i][2], ahi[i][3], bl0, bl1);
                mma8(acc[i][j], alo[i][0], alo[i][1], alo[i][2], alo[i][3], bh0, bh1);
            }
        }
    }
}

// load one K-quarter (32 rows) of W, split hi/lo: Wg[(h*32+kk)*128+n] -> [kk*132+n]
__device__ __forceinline__ void load_w_quarter(
    float* smf, const float* __restrict__ Wg, int h, int tid)
{
    uint32_t* wh = (uint32_t*)smf + SWH;
    uint32_t* wl = (uint32_t*)smf + SWL;
    const float* src = Wg + (size_t)h * 32 * 128;
    #pragma unroll
    for (int it = 0; it < 16; it++) {
        int idx = tid + it * 256;        // 4096 elems
        int kk = idx >> 7, n = idx & 127;
        uint32_t hi, lo;
        cvt_hilo(src[idx], hi, lo);
        wh[kk * 132 + n] = hi;
        wl[kk * 132 + n] = lo;
    }
}

// ---------------- GEMM kernel: Z = relu(A@W1+b1)@W2 + b2 + epilogue ----------------
__global__ void __launch_bounds__(256, 2) gemm_mma(
    const float* __restrict__ W1, const float* __restrict__ b1,
    const float* __restrict__ W2, const float* __restrict__ b2,
    int layer, float* __restrict__ out, const void* __restrict__ batch, int last)
{
    extern __shared__ float smf[];
    const int tid = threadIdx.x;
    const int wid = tid >> 5, lane = tid & 31;
    const int g = lane >> 2, t = lane & 3;
    const int wr = (wid >> 2) * 64;
    const int wc = (wid & 3) * 32;
    const int r0 = blockIdx.x * MT;

    if (tid < 128) {
        smf[SB1 + tid] = b1[tid];
        smf[SB2 + tid] = b2[tid];
        smf[SSUM + tid] = 0.0f;
        smf[SSQ + tid] = 0.0f;
    }

    // fill A tile (fp32) from g_a
    {
        const float4* a4 = (const float4*)g_a;
        #pragma unroll
        for (int it = 0; it < 16; it++) {
            int idx = tid + it * 256;       // 4096 float4
            int m = idx >> 5, kq = idx & 31;
            float4 v = make_float4(0.f, 0.f, 0.f, 0.f);
            if (r0 + m < N_NODES) v = a4[(size_t)(r0 + m) * 32 + kq];
            *(float4*)&smf[SA + m * 132 + kq * 4] = v;
        }
    }

    float acc[4][4][4];
    #pragma unroll
    for (int i = 0; i < 4; i++)
        #pragma unroll
        for (int j = 0; j < 4; j++)
            #pragma unroll
            for (int c = 0; c < 4; c++) acc[i][j][c] = 0.0f;

    // ---- GEMM1 over four K-quarters ----
    #pragma unroll 1
    for (int h = 0; h < 4; h++) {
        __syncthreads();
        load_w_quarter(smf, W1, h, tid);
        __syncthreads();
        gemm_quarter(smf, acc, wr, wc, g, t, h);
    }
    __syncthreads();

    // T = relu(acc + b1) -> sA
    #pragma unroll
    for (int i = 0; i < 4; i++) {
        #pragma unroll
        for (int j = 0; j < 4; j++) {
            int c0 = wc + j * 8 + 2 * t;
            int rA = wr + i * 16 + g;
            float bb0 = smf[SB1 + c0], bb1 = smf[SB1 + c0 + 1];
            float2 u0 = make_float2(fmaxf(acc[i][j][0] + bb0, 0.0f),
                                    fmaxf(acc[i][j][1] + bb1, 0.0f));
            float2 u1 = make_float2(fmaxf(acc[i][j][2] + bb0, 0.0f),
                                    fmaxf(acc[i][j][3] + bb1, 0.0f));
            *(float2*)&smf[SA + rA * 132 + c0] = u0;
            *(float2*)&smf[SA + (rA + 8) * 132 + c0] = u1;
            acc[i][j][0] = 0.0f; acc[i][j][1] = 0.0f;
            acc[i][j][2] = 0.0f; acc[i][j][3] = 0.0f;
        }
    }

    // ---- GEMM2 over four K-quarters ----
    #pragma unroll 1
    for (int h = 0; h < 4; h++) {
        __syncthreads();
        load_w_quarter(smf, W2, h, tid);
        __syncthreads();
        gemm_quarter(smf, acc, wr, wc, g, t, h);
    }
    __syncthreads();

    // stage z = acc + b2 into sA
    #pragma unroll
    for (int i = 0; i < 4; i++) {
        #pragma unroll
        for (int j = 0; j < 4; j++) {
            int c0 = wc + j * 8 + 2 * t;
            int rA = wr + i * 16 + g;
            float bb0 = smf[SB2 + c0], bb1 = smf[SB2 + c0 + 1];
            float2 u0 = make_float2(acc[i][j][0] + bb0, acc[i][j][1] + bb1);
            float2 u1 = make_float2(acc[i][j][2] + bb0, acc[i][j][3] + bb1);
            *(float2*)&smf[SA + rA * 132 + c0] = u0;
            *(float2*)&smf[SA + (rA + 8) * 132 + c0] = u1;
        }
    }
    __syncthreads();

    const int col4 = tid & 31;
    if (!last) {
        float s[4] = {0, 0, 0, 0}, q[4] = {0, 0, 0, 0};
        #pragma unroll
        for (int it = 0; it < 16; it++) {
            int row = (tid >> 5) + it * 8;
            int r = r0 + row;
            if (r < N_NODES) {
                float4 z4 = *(const float4*)&smf[SA + row * 132 + col4 * 4];
                *(float4*)&g_z[(size_t)r * D + col4 * 4] = z4;
                s[0] += z4.x; q[0] += z4.x * z4.x;
                s[1] += z4.y; q[1] += z4.y * z4.y;
                s[2] += z4.z; q[2] += z4.z * z4.z;
                s[3] += z4.w; q[3] += z4.w * z4.w;
            }
        }
        #pragma unroll
        for (int j = 0; j < 4; j++) {
            atomicAdd(&smf[SSUM + col4 * 4 + j], s[j]);
            atomicAdd(&smf[SSQ + col4 * 4 + j], q[j]);
        }
        __syncthreads();
        if (tid < 128) {
            atomicAdd(&g_stats[layer * 2 * D + tid], smf[SSUM + tid]);
            atomicAdd(&g_stats[layer * 2 * D + D + tid], smf[SSQ + tid]);
        }
    } else {
        int gcur = -1;
        float a0 = 0, a1 = 0, a2 = 0, a3 = 0;
        #pragma unroll 1
        for (int it = 0; it < 16; it++) {
            int row = (tid >> 5) + it * 8;
            int r = r0 + row;
            if (r < N_NODES) {
                float4 z4 = *(const float4*)&smf[SA + row * 132 + col4 * 4];
                int gg = load_idx(batch, r);
                if (gg == gcur) {
                    a0 += z4.x; a1 += z4.y; a2 += z4.z; a3 += z4.w;
                } else {
                    if (gcur >= 0 && gcur < NUM_GRAPHS) {
                        atomicAdd(&out[gcur * D + col4 * 4 + 0], a0);
                        atomicAdd(&out[gcur * D + col4 * 4 + 1], a1);
                        atomicAdd(&out[gcur * D + col4 * 4 + 2], a2);
                        atomicAdd(&out[gcur * D + col4 * 4 + 3], a3);
                    }
                    gcur = gg; a0 = z4.x; a1 = z4.y; a2 = z4.z; a3 = z4.w;
                }
            }
        }
        if (gcur >= 0 && gcur < NUM_GRAPHS) {
            atomicAdd(&out[gcur * D + col4 * 4 + 0], a0);
            atomicAdd(&out[gcur * D + col4 * 4 + 1], a1);
            atomicAdd(&out[gcur * D + col4 * 4 + 2], a2);
            atomicAdd(&out[gcur * D + col4 * 4 + 3], a3);
        }
    }
}

// ---------------- launch ----------------
extern "C" void kernel_launch(void* const* d_in, const int* in_sizes, int n_in,
                              void* d_out, int out_size) {
    const float* x     = (const float*)d_in[0];
    const void*  ei    = d_in[1];
    const void*  batch = d_in[2];
    const float* W1    = (const float*)d_in[3];
    const float* b1    = (const float*)d_in[4];
    const float* W2    = (const float*)d_in[5];
    const float* b2    = (const float*)d_in[6];
    const float* eps   = (const float*)d_in[7];
    const float* gamma = (const float*)d_in[8];
    const float* beta  = (const float*)d_in[9];
    float* out = (float*)d_out;

    cudaFuncSetAttribute(gemm_mma, cudaFuncAttributeMaxDynamicSharedMemorySize,
                         SM_BYTES);

    detect_zero_kernel<<<64, 256>>>(ei, out);
    hist_kernel<<<(N_EDGES + 255) / 256, 256>>>(ei);
    scan_part_kernel<<<SCAN_NBLK, SCAN_BLK>>>();
    scan_topadd_kernel<<<SCAN_NBLK, SCAN_BLK>>>();
    fill_kernel<<<(N_EDGES + 255) / 256, 256>>>(ei);

    for (int i = 0; i < N_LAYERS; i++) {
        gather_kernel<<<(N_NODES + 7) / 8, 256>>>(
            x, eps, gamma + (i > 0 ? (i - 1) * D : 0),
            beta + (i > 0 ? (i - 1) * D : 0), i);
        gemm_mma<<<GEMM_GRID, 256, SM_BYTES>>>(
            W1 + i * D * D, b1 + i * D, W2 + i * D * D, b2 + i * D,
            i, out, batch, (i == N_LAYERS - 1) ? 1 : 0);
    }
}

// round 8
// speedup vs baseline: 1.3700x; 1.3365x over previous
#include <cuda_runtime.h>
#include <cuda_fp16.h>
#include <cstdint>

#define N_NODES 50000
#define N_EDGES 800000
#define D 128
#define NUM_GRAPHS 128
#define N_LAYERS 4
#define BN_EPS 1e-5f

#define MT 128
#define GEMM_GRID ((N_NODES + MT - 1) / MT)

#define SCAN_BLK 1024
#define SCAN_NBLK ((N_NODES + SCAN_BLK - 1) / SCAN_BLK)

// ---- smem byte map for gemm_mma (occ 1) ----
// floats: b1(512) b2(512) ssum(512) ssq(512) = 2048 B
// A hi/lo: fp16 128 x 136 halves = 34816 B each
// W hi/lo ([n][k] transposed): fp16 128 x 136 = 34816 B each
#define AH_B 2048
#define AL_B (AH_B + 34816)
#define WH_B (AL_B + 34816)
#define WL_B (WH_B + 34816)
#define SM_BYTES (WL_B + 34816)   // 141312
// float indices
#define SB1F  0
#define SB2F  128
#define SSUMF 256
#define SSQF  384
#define SZST  512                 // Z staging fp32 (reuses AH+AL region), stride 132

// ---------------- device scratch ----------------
__device__ float  g_a[(size_t)N_NODES * D];     // aggregated GIN input (fp32)
__device__ __half g_h16[(size_t)N_NODES * D];   // h (x or pre-BN z) in fp16
__device__ int    g_deg[N_NODES];
__device__ int    g_ptr[N_NODES + 1];
__device__ int    g_cursor[N_NODES];
__device__ int    g_csr[N_EDGES];
__device__ int    g_bsum[SCAN_NBLK];
__device__ float  g_stats[(N_LAYERS - 1) * 2 * D];
__device__ int    g_idx64;

__device__ __forceinline__ int load_idx(const void* p, int i) {
    if (g_idx64) return (int)((const long long*)p)[i];
    return ((const int*)p)[i];
}

__device__ __forceinline__ void f16_hilo(float v, __half& hi, __half& lo) {
    hi = __float2half_rn(v);
    lo = __float2half_rn(v - __half2float(hi));
}
__device__ __forceinline__ uint32_t pack_h2(__half a, __half b) {
    __half2 h = __halves2half2(a, b);
    return *(uint32_t*)&h;
}

__device__ __forceinline__ void mma16(float* c, uint32_t a0, uint32_t a1,
                                      uint32_t a2, uint32_t a3,
                                      uint32_t b0, uint32_t b1) {
    asm volatile(
        "mma.sync.aligned.m16n8k16.row.col.f32.f16.f16.f32 "
        "{%0,%1,%2,%3}, {%4,%5,%6,%7}, {%8,%9}, {%0,%1,%2,%3};"
        : "+f"(c[0]), "+f"(c[1]), "+f"(c[2]), "+f"(c[3])
        : "r"(a0), "r"(a1), "r"(a2), "r"(a3), "r"(b0), "r"(b1));
}

// ---------------- detect dtype + zero scratch + x -> fp16 (launch 0) ----------------
__global__ void detect_zero_kernel(const void* ei, const float* __restrict__ x,
                                   float* __restrict__ out) {
    int i = blockIdx.x * blockDim.x + threadIdx.x;
    int stride = gridDim.x * blockDim.x;
    for (int t = i; t < N_NODES; t += stride) g_deg[t] = 0;
    for (int t = i; t < (N_LAYERS - 1) * 2 * D; t += stride) g_stats[t] = 0.0f;
    for (int t = i; t < NUM_GRAPHS * D; t += stride) out[t] = 0.0f;
    // convert x -> g_h16
    for (int t = i; t < N_NODES * (D / 2); t += stride) {
        float2 v = ((const float2*)x)[t];
        ((__half2*)g_h16)[t] = __floats2half2_rn(v.x, v.y);
    }

    if (blockIdx.x == 0) {
        __shared__ int any_nonzero;
        const int* a = (const int*)ei;
        if (threadIdx.x == 0) any_nonzero = 0;
        __syncthreads();
        int step = (2 * N_EDGES) / 256;
        int pos = (threadIdx.x * step) | 1;
        if (a[pos] != 0) any_nonzero = 1;
        __syncthreads();
        if (threadIdx.x == 0) g_idx64 = any_nonzero ? 0 : 1;
    }
}

// ---------------- CSR build ----------------
__global__ void hist_kernel(const void* __restrict__ ei) {
    int e = blockIdx.x * blockDim.x + threadIdx.x;
    if (e < N_EDGES) {
        int dst = load_idx(ei, N_EDGES + e);
        if (dst >= 0 && dst < N_NODES) atomicAdd(&g_deg[dst], 1);
    }
}

__global__ void scan_part_kernel() {
    __shared__ int wsum[32];
    const int tid = threadIdx.x;
    const int lane = tid & 31, wid = tid >> 5;
    int idx = blockIdx.x * SCAN_BLK + tid;
    int v = (idx < N_NODES) ? g_deg[idx] : 0;
    int s = v;
    #pragma unroll
    for (int off = 1; off < 32; off <<= 1) {
        int t = __shfl_up_sync(0xffffffffu, s, off);
        if (lane >= off) s += t;
    }
    if (lane == 31) wsum[wid] = s;
    __syncthreads();
    if (wid == 0) {
        int ws = wsum[lane];
        #pragma unroll
        for (int off = 1; off < 32; off <<= 1) {
            int t = __shfl_up_sync(0xffffffffu, ws, off);
            if (lane >= off) ws += t;
        }
        wsum[lane] = ws;
    }
    __syncthreads();
    int incl = s + ((wid > 0) ? wsum[wid - 1] : 0);
    if (idx < N_NODES) g_ptr[idx + 1] = incl;
    if (tid == SCAN_BLK - 1) g_bsum[blockIdx.x] = incl;
}

__global__ void scan_topadd_kernel() {
    __shared__ int carry_s;
    const int tid = threadIdx.x;
    if (tid == 0) {
        int run = 0;
        for (int b = 0; b < (int)blockIdx.x; b++) run += g_bsum[b];
        carry_s = run;
    }
    __syncthreads();
    int idx = blockIdx.x * SCAN_BLK + tid;
    if (idx < N_NODES) {
        int p = g_ptr[idx + 1] + carry_s;
        g_ptr[idx + 1] = p;
        g_cursor[idx + 1] = p;
    }
    if (idx == 0) { g_ptr[0] = 0; g_cursor[0] = 0; }
}

__global__ void fill_kernel(const void* __restrict__ ei) {
    int e = blockIdx.x * blockDim.x + threadIdx.x;
    if (e >= N_EDGES) return;
    int src = load_idx(ei, e);
    int dst = load_idx(ei, N_EDGES + e);
    if (dst < 0 || dst >= N_NODES || src < 0 || src >= N_NODES) return;
    int p = atomicAdd(&g_cursor[dst], 1);
    if (p >= 0 && p < N_EDGES) g_csr[p] = src;
}

// ---------------- gather (fp16 source) with fused BN+ReLU ----------------
__device__ __forceinline__ float4 ldh4(size_t ridx, int lane) {
    uint2 u = ((const uint2*)g_h16)[ridx * 32 + lane];
    float2 f0 = __half22float2(*(__half2*)&u.x);
    float2 f1 = __half22float2(*(__half2*)&u.y);
    return make_float4(f0.x, f0.y, f1.x, f1.y);
}

__global__ void __launch_bounds__(256) gather_kernel(
    const float* __restrict__ eps_arr,
    const float* __restrict__ gamma, const float* __restrict__ beta,
    int layer)
{
    __shared__ float ssc[D], ssh[D];
    const int tid = threadIdx.x;
    const int apply_bn = (layer > 0);
    if (apply_bn && tid < D) {
        const float* stats = &g_stats[(layer - 1) * 2 * D];
        const float invN = 1.0f / (float)N_NODES;
        float mu = stats[tid] * invN;
        float var = stats[D + tid] * invN - mu * mu;
        float sc = rsqrtf(var + BN_EPS) * gamma[tid];
        ssc[tid] = sc;
        ssh[tid] = beta[tid] - mu * sc;
    }
    __syncthreads();

    const int lane = tid & 31, wid = tid >> 5;
    const int r = blockIdx.x * 8 + wid;
    if (r >= N_NODES) return;

    float4 sc4 = make_float4(1.f, 1.f, 1.f, 1.f);
    float4 sh4 = make_float4(0.f, 0.f, 0.f, 0.f);
    if (apply_bn) {
        sc4 = *(const float4*)&ssc[lane * 4];
        sh4 = *(const float4*)&ssh[lane * 4];
    }
    const float ep = 1.0f + eps_arr[layer];

    float4 v = ldh4((size_t)r, lane);
    float4 acc;
    if (apply_bn) {
        acc.x = ep * fmaxf(v.x * sc4.x + sh4.x, 0.0f);
        acc.y = ep * fmaxf(v.y * sc4.y + sh4.y, 0.0f);
        acc.z = ep * fmaxf(v.z * sc4.z + sh4.z, 0.0f);
        acc.w = ep * fmaxf(v.w * sc4.w + sh4.w, 0.0f);
    } else {
        acc.x = ep * v.x; acc.y = ep * v.y; acc.z = ep * v.z; acc.w = ep * v.w;
    }

    const int e0 = g_ptr[r], end = g_ptr[r + 1];
    for (int base = e0; base < end; base += 32) {
        const int cnt = min(end - base, 32);
        int myidx = (lane < cnt) ? g_csr[base + lane] : 0;
        int t0 = 0;
        for (; t0 + 8 <= cnt; t0 += 8) {
            int ss[8];
            #pragma unroll
            for (int t = 0; t < 8; t++) ss[t] = __shfl_sync(0xffffffffu, myidx, t0 + t);
            float4 u[8];
            #pragma unroll
            for (int t = 0; t < 8; t++) u[t] = ldh4((size_t)ss[t], lane);
            #pragma unroll
            for (int t = 0; t < 8; t++) {
                if (apply_bn) {
                    acc.x += fmaxf(u[t].x * sc4.x + sh4.x, 0.0f);
                    acc.y += fmaxf(u[t].y * sc4.y + sh4.y, 0.0f);
                    acc.z += fmaxf(u[t].z * sc4.z + sh4.z, 0.0f);
                    acc.w += fmaxf(u[t].w * sc4.w + sh4.w, 0.0f);
                } else {
                    acc.x += u[t].x; acc.y += u[t].y;
                    acc.z += u[t].z; acc.w += u[t].w;
                }
            }
        }
        for (; t0 < cnt; t0++) {
            int s = __shfl_sync(0xffffffffu, myidx, t0);
            float4 u = ldh4((size_t)s, lane);
            if (apply_bn) {
                acc.x += fmaxf(u.x * sc4.x + sh4.x, 0.0f);
                acc.y += fmaxf(u.y * sc4.y + sh4.y, 0.0f);
                acc.z += fmaxf(u.z * sc4.z + sh4.z, 0.0f);
                acc.w += fmaxf(u.w * sc4.w + sh4.w, 0.0f);
            } else {
                acc.x += u.x; acc.y += u.y; acc.z += u.z; acc.w += u.w;
            }
        }
    }
    ((float4*)g_a)[r * 32 + lane] = acc;
}

// ---------------- W fill: global [k][n] fp32 -> smem [n][k] fp16 hi/lo ----------------
__device__ __forceinline__ void fill_w(char* smem, const float* __restrict__ Wg,
                                       int wid, int lane) {
    #pragma unroll 1
    for (int s = 0; s < 8; s++) {
        int task = wid + s * 8;          // 0..63
        int k0 = (task >> 2) * 8;        // 0,8,...,120
        int n = (task & 3) * 32 + lane;  // 0..127
        float w[8];
        #pragma unroll
        for (int r = 0; r < 8; r++) w[r] = Wg[(size_t)(k0 + r) * 128 + n];
        __half hh[8], hl[8];
        #pragma unroll
        for (int r = 0; r < 8; r++) f16_hilo(w[r], hh[r], hl[r]);
        uint4 uh, ul;
        uh.x = pack_h2(hh[0], hh[1]); uh.y = pack_h2(hh[2], hh[3]);
        uh.z = pack_h2(hh[4], hh[5]); uh.w = pack_h2(hh[6], hh[7]);
        ul.x = pack_h2(hl[0], hl[1]); ul.y = pack_h2(hl[2], hl[3]);
        ul.z = pack_h2(hl[4], hl[5]); ul.w = pack_h2(hl[6], hl[7]);
        *(uint4*)(smem + WH_B + ((size_t)n * 136 + k0) * 2) = uh;
        *(uint4*)(smem + WL_B + ((size_t)n * 136 + k0) * 2) = ul;
    }
}

// ---------------- one 128x128x128 GEMM (fp16 hi/lo 3-pass, fp32 acc) ----------------
__device__ __forceinline__ void gemm128(const char* __restrict__ smem,
                                        float (&acc)[4][4][4],
                                        int wr, int wc, int g, int t)
{
    #pragma unroll 1
    for (int ks = 0; ks < 8; ks++) {
        const int k0 = ks * 16;
        uint32_t ah[4][4], al[4][4];
        #pragma unroll
        for (int i = 0; i < 4; i++) {
            int ob = ((wr + i * 16 + g) * 136 + k0 + 2 * t) * 2;
            ah[i][0] = *(const uint32_t*)(smem + AH_B + ob);
            ah[i][1] = *(const uint32_t*)(smem + AH_B + ob + 2176);
            ah[i][2] = *(const uint32_t*)(smem + AH_B + ob + 16);
            ah[i][3] = *(const uint32_t*)(smem + AH_B + ob + 2192);
            al[i][0] = *(const uint32_t*)(smem + AL_B + ob);
            al[i][1] = *(const uint32_t*)(smem + AL_B + ob + 2176);
            al[i][2] = *(const uint32_t*)(smem + AL_B + ob + 16);
            al[i][3] = *(const uint32_t*)(smem + AL_B + ob + 2192);
        }
        #pragma unroll
        for (int j = 0; j < 4; j++) {
            int wb = ((wc + j * 8 + g) * 136 + k0 + 2 * t) * 2;
            uint32_t bh0 = *(const uint32_t*)(smem + WH_B + wb);
            uint32_t bh1 = *(const uint32_t*)(smem + WH_B + wb + 16);
            uint32_t bl0 = *(const uint32_t*)(smem + WL_B + wb);
            uint32_t bl1 = *(const uint32_t*)(smem + WL_B + wb + 16);
            #pragma unroll
            for (int i = 0; i < 4; i++) {
                mma16(acc[i][j], ah[i][0], ah[i][1], ah[i][2], ah[i][3], bh0, bh1);
                mma16(acc[i][j], ah[i][0], ah[i][1], ah[i][2], ah[i][3], bl0, bl1);
                mma16(acc[i][j], al[i][0], al[i][1], al[i][2], al[i][3], bh0, bh1);
            }
        }
    }
}

// ---------------- GEMM kernel: Z = relu(A@W1+b1)@W2 + b2 + epilogue ----------------
__global__ void __launch_bounds__(256, 1) gemm_mma(
    const float* __restrict__ W1, const float* __restrict__ b1,
    const float* __restrict__ W2, const float* __restrict__ b2,
    int layer, float* __restrict__ out, const void* __restrict__ batch, int last)
{
    extern __shared__ char smem[];
    float* smf = (float*)smem;
    const int tid = threadIdx.x;
    const int wid = tid >> 5, lane = tid & 31;
    const int g = lane >> 2, t = lane & 3;
    const int wr = (wid >> 2) * 64;
    const int wc = (wid & 3) * 32;
    const int r0 = blockIdx.x * MT;

    if (tid < 128) {
        smf[SB1F + tid] = b1[tid];
        smf[SB2F + tid] = b2[tid];
        smf[SSUMF + tid] = 0.0f;
        smf[SSQF + tid] = 0.0f;
    }

    // A fill: fp32 g_a -> fp16 hi/lo in smem
    #pragma unroll
    for (int it = 0; it < 32; it++) {
        int idx = tid + it * 256;       // 8192 (m, c2) pairs
        int m = idx >> 6, c2 = idx & 63;
        float2 v = make_float2(0.f, 0.f);
        if (r0 + m < N_NODES) v = ((const float2*)g_a)[(size_t)(r0 + m) * 64 + c2];
        __half h0, l0, h1, l1;
        f16_hilo(v.x, h0, l0);
        f16_hilo(v.y, h1, l1);
        int ob = (m * 136 + 2 * c2) * 2;
        *(uint32_t*)(smem + AH_B + ob) = pack_h2(h0, h1);
        *(uint32_t*)(smem + AL_B + ob) = pack_h2(l0, l1);
    }
    fill_w(smem, W1, wid, lane);
    __syncthreads();

    float acc[4][4][4];
    #pragma unroll
    for (int i = 0; i < 4; i++)
        #pragma unroll
        for (int j = 0; j < 4; j++)
            #pragma unroll
            for (int c = 0; c < 4; c++) acc[i][j][c] = 0.0f;

    gemm128(smem, acc, wr, wc, g, t);
    __syncthreads();

    // T = relu(acc + b1) -> split back into A hi/lo; load W2
    #pragma unroll
    for (int i = 0; i < 4; i++) {
        #pragma unroll
        for (int j = 0; j < 4; j++) {
            int c0 = wc + j * 8 + 2 * t;
            int rA = wr + i * 16 + g;
            float bb0 = smf[SB1F + c0], bb1 = smf[SB1F + c0 + 1];
            float v00 = fmaxf(acc[i][j][0] + bb0, 0.0f);
            float v01 = fmaxf(acc[i][j][1] + bb1, 0.0f);
            float v10 = fmaxf(acc[i][j][2] + bb0, 0.0f);
            float v11 = fmaxf(acc[i][j][3] + bb1, 0.0f);
            __half h0, l0, h1, l1;
            f16_hilo(v00, h0, l0); f16_hilo(v01, h1, l1);
            int ob0 = (rA * 136 + c0) * 2;
            *(uint32_t*)(smem + AH_B + ob0) = pack_h2(h0, h1);
            *(uint32_t*)(smem + AL_B + ob0) = pack_h2(l0, l1);
            f16_hilo(v10, h0, l0); f16_hilo(v11, h1, l1);
            int ob1 = ((rA + 8) * 136 + c0) * 2;
            *(uint32_t*)(smem + AH_B + ob1) = pack_h2(h0, h1);
            *(uint32_t*)(smem + AL_B + ob1) = pack_h2(l0, l1);
            acc[i][j][0] = 0.0f; acc[i][j][1] = 0.0f;
            acc[i][j][2] = 0.0f; acc[i][j][3] = 0.0f;
        }
    }
    fill_w(smem, W2, wid, lane);
    __syncthreads();

    gemm128(smem, acc, wr, wc, g, t);
    __syncthreads();

    // stage z = acc + b2 into fp32 staging (reuses A region)
    #pragma unroll
    for (int i = 0; i < 4; i++) {
        #pragma unroll
        for (int j = 0; j < 4; j++) {
            int c0 = wc + j * 8 + 2 * t;
            int rA = wr + i * 16 + g;
            float bb0 = smf[SB2F + c0], bb1 = smf[SB2F + c0 + 1];
            float2 u0 = make_float2(acc[i][j][0] + bb0, acc[i][j][1] + bb1);
            float2 u1 = make_float2(acc[i][j][2] + bb0, acc[i][j][3] + bb1);
            *(float2*)&smf[SZST + rA * 132 + c0] = u0;
            *(float2*)&smf[SZST + (rA + 8) * 132 + c0] = u1;
        }
    }
    __syncthreads();

    const int col4 = tid & 31;
    if (!last) {
        float s[4] = {0, 0, 0, 0}, q[4] = {0, 0, 0, 0};
        #pragma unroll
        for (int it = 0; it < 16; it++) {
            int row = (tid >> 5) + it * 8;
            int r = r0 + row;
            if (r < N_NODES) {
                float4 z4 = *(const float4*)&smf[SZST + row * 132 + col4 * 4];
                uint2 packed;
                packed.x = pack_h2(__float2half_rn(z4.x), __float2half_rn(z4.y));
                packed.y = pack_h2(__float2half_rn(z4.z), __float2half_rn(z4.w));
                *(uint2*)&g_h16[(size_t)r * D + col4 * 4] = packed;
                s[0] += z4.x; q[0] += z4.x * z4.x;
                s[1] += z4.y; q[1] += z4.y * z4.y;
                s[2] += z4.z; q[2] += z4.z * z4.z;
                s[3] += z4.w; q[3] += z4.w * z4.w;
            }
        }
        #pragma unroll
        for (int j = 0; j < 4; j++) {
            atomicAdd(&smf[SSUMF + col4 * 4 + j], s[j]);
            atomicAdd(&smf[SSQF + col4 * 4 + j], q[j]);
        }
        __syncthreads();
        if (tid < 128) {
            atomicAdd(&g_stats[layer * 2 * D + tid], smf[SSUMF + tid]);
            atomicAdd(&g_stats[layer * 2 * D + D + tid], smf[SSQF + tid]);
        }
    } else {
        int gcur = -1;
        float a0 = 0, a1 = 0, a2 = 0, a3 = 0;
        #pragma unroll 1
        for (int it = 0; it < 16; it++) {
            int row = (tid >> 5) + it * 8;
            int r = r0 + row;
            if (r < N_NODES) {
                float4 z4 = *(const float4*)&smf[SZST + row * 132 + col4 * 4];
                int gg = load_idx(batch, r);
                if (gg == gcur) {
                    a0 += z4.x; a1 += z4.y; a2 += z4.z; a3 += z4.w;
                } else {
                    if (gcur >= 0 && gcur < NUM_GRAPHS) {
                        atomicAdd(&out[gcur * D + col4 * 4 + 0], a0);
                        atomicAdd(&out[gcur * D + col4 * 4 + 1], a1);
                        atomicAdd(&out[gcur * D + col4 * 4 + 2], a2);
                        atomicAdd(&out[gcur * D + col4 * 4 + 3], a3);
                    }
                    gcur = gg; a0 = z4.x; a1 = z4.y; a2 = z4.z; a3 = z4.w;
                }
            }
        }
        if (gcur >= 0 && gcur < NUM_GRAPHS) {
            atomicAdd(&out[gcur * D + col4 * 4 + 0], a0);
            atomicAdd(&out[gcur * D + col4 * 4 + 1], a1);
            atomicAdd(&out[gcur * D + col4 * 4 + 2], a2);
            atomicAdd(&out[gcur * D + col4 * 4 + 3], a3);
        }
    }
}

// ---------------- launch ----------------
extern "C" void kernel_launch(void* const* d_in, const int* in_sizes, int n_in,
                              void* d_out, int out_size) {
    const float* x     = (const float*)d_in[0];
    const void*  ei    = d_in[1];
    const void*  batch = d_in[2];
    const float* W1    = (const float*)d_in[3];
    const float* b1    = (const float*)d_in[4];
    const float* W2    = (const float*)d_in[5];
    const float* b2    = (const float*)d_in[6];
    const float* eps   = (const float*)d_in[7];
    const float* gamma = (const float*)d_in[8];
    const float* beta  = (const float*)d_in[9];
    float* out = (float*)d_out;

    cudaFuncSetAttribute(gemm_mma, cudaFuncAttributeMaxDynamicSharedMemorySize,
                         SM_BYTES);

    detect_zero_kernel<<<256, 256>>>(ei, x, out);
    hist_kernel<<<(N_EDGES + 255) / 256, 256>>>(ei);
    scan_part_kernel<<<SCAN_NBLK, SCAN_BLK>>>();
    scan_topadd_kernel<<<SCAN_NBLK, SCAN_BLK>>>();
    fill_kernel<<<(N_EDGES + 255) / 256, 256>>>(ei);

    for (int i = 0; i < N_LAYERS; i++) {
        gather_kernel<<<(N_NODES + 7) / 8, 256>>>(
            eps, gamma + (i > 0 ? (i - 1) * D : 0),
            beta + (i > 0 ? (i - 1) * D : 0), i);
        gemm_mma<<<GEMM_GRID, 256, SM_BYTES>>>(
            W1 + i * D * D, b1 + i * D, W2 + i * D * D, b2 + i * D,
            i, out, batch, (i == N_LAYERS - 1) ? 1 : 0);
    }
}